// round 13
// baseline (speedup 1.0000x reference)
#include <cuda_runtime.h>
#include <cuda_bf16.h>
#include <cstdint>
#include <cmath>

// Problem constants
#define S_LEN   1024
#define DMODEL  1024
#define H_NUM   16
#define DH      64
#define BATCH   2
#define NCH     32     // chunks along S
#define CHS     32     // chunk length (S_LEN / NCH)

// Scratch (static device globals; no allocation allowed)
__device__ float g_qkv[(size_t)BATCH * S_LEN * 3 * DMODEL];   // 25.2 MB
__device__ float g_ckv[BATCH * H_NUM * 5 * NCH * DH];         // kv chunk sums -> exclusive prefix
__device__ float g_crk[BATCH * H_NUM * 5 * NCH];              // rk chunk sums -> exclusive prefix

// bf16 hi/lo split operands
__device__ __nv_bfloat16 g_xh[(size_t)BATCH * S_LEN * DMODEL];
__device__ __nv_bfloat16 g_xl[(size_t)BATCH * S_LEN * DMODEL];
__device__ __nv_bfloat16 g_wih[(size_t)3 * DMODEL * DMODEL];
__device__ __nv_bfloat16 g_wil[(size_t)3 * DMODEL * DMODEL];
__device__ __nv_bfloat16 g_woh[(size_t)DMODEL * DMODEL];
__device__ __nv_bfloat16 g_wol[(size_t)DMODEL * DMODEL];
__device__ __nv_bfloat16 g_ath[(size_t)BATCH * S_LEN * DMODEL];
__device__ __nv_bfloat16 g_atl[(size_t)BATCH * S_LEN * DMODEL];

struct Betas { float b[5]; };

__device__ __forceinline__ float clampx(float x) {
    return fminf(fmaxf(x, -1.0f + 1e-6f), 1.0f - 1e-6f);
}

__device__ __forceinline__ void cheb5(float x, float t[5]) {
    float x2 = x + x;
    float t1 = x;
    float t2 = x2 * t1 - 1.0f;
    float t3 = x2 * t2 - t1;
    float t4 = x2 * t3 - t2;
    float t5 = x2 * t4 - t3;
    t[0] = t1; t[1] = t2; t[2] = t3; t[3] = t4; t[4] = t5;
}

__device__ __forceinline__ unsigned pack2(__nv_bfloat16 a, __nv_bfloat16 b) {
    __nv_bfloat162 t(a, b);
    return *reinterpret_cast<unsigned*>(&t);
}

__device__ __forceinline__ void ldsm4(unsigned& r0, unsigned& r1, unsigned& r2, unsigned& r3,
                                      unsigned addr) {
    asm volatile("ldmatrix.sync.aligned.m8n8.x4.shared.b16 {%0,%1,%2,%3}, [%4];"
                 : "=r"(r0), "=r"(r1), "=r"(r2), "=r"(r3) : "r"(addr));
}

__device__ __forceinline__ void mma_bf16(float c[4],
                                         unsigned a0, unsigned a1, unsigned a2, unsigned a3,
                                         unsigned b0, unsigned b1) {
    asm volatile(
        "mma.sync.aligned.m16n8k16.row.col.f32.bf16.bf16.f32 "
        "{%0,%1,%2,%3}, {%4,%5,%6,%7}, {%8,%9}, {%0,%1,%2,%3};"
        : "+f"(c[0]), "+f"(c[1]), "+f"(c[2]), "+f"(c[3])
        : "r"(a0), "r"(a1), "r"(a2), "r"(a3), "r"(b0), "r"(b1));
}

#define CP16(dst, src) \
    asm volatile("cp.async.cg.shared.global [%0], [%1], 16;" :: "r"(dst), "l"(src))
#define CP_COMMIT() asm volatile("cp.async.commit_group;")
#define CP_WAIT2()  asm volatile("cp.async.wait_group 2;")
#define CP_WAIT0()  asm volatile("cp.async.wait_group 0;")

// swizzled byte offset inside a 128x32 bf16 tile (64B rows).
__device__ __forceinline__ unsigned swz(int m, int cbyte) {
    return (unsigned)((m << 6) + (cbyte ^ (((m >> 1) & 3) << 4)));
}

// ---------------------------------------------------------------------------
// split_one: f32 -> bf16 hi + bf16 lo residual, one tensor per launch
// ---------------------------------------------------------------------------
__global__ __launch_bounds__(256) void split_one(
    const float* __restrict__ src, __nv_bfloat16* __restrict__ hi,
    __nv_bfloat16* __restrict__ lo, int n)
{
    int i = (blockIdx.x * blockDim.x + threadIdx.x) * 4;
    if (i >= n) return;

    float4 v = *(const float4*)(src + i);
    __nv_bfloat16 h0 = __float2bfloat16(v.x), h1 = __float2bfloat16(v.y);
    __nv_bfloat16 h2 = __float2bfloat16(v.z), h3 = __float2bfloat16(v.w);
    __nv_bfloat16 l0 = __float2bfloat16(v.x - __bfloat162float(h0));
    __nv_bfloat16 l1 = __float2bfloat16(v.y - __bfloat162float(h1));
    __nv_bfloat16 l2 = __float2bfloat16(v.z - __bfloat162float(h2));
    __nv_bfloat16 l3 = __float2bfloat16(v.w - __bfloat162float(h3));
    *(uint2*)(hi + i) = make_uint2(pack2(h0, h1), pack2(h2, h3));
    *(uint2*)(lo + i) = make_uint2(pack2(l0, l1), pack2(l2, l3));
}

// ---------------------------------------------------------------------------
// bf16x3 GEMM, pre-split operands, 4-stage cp.async pipeline (1 sync/tile):
//   C[M,N] = (Ah+Al)[M,K] @ (Bh+Bl)[N,K]^T  (drop Al*Bl)
// BM=BN=128, BK=32, 256 threads (8 warps 2x4), warp tile 64x32.
// Dynamic smem: 4 stages x 32KB (Ah|Al|Bh|Bl 8KB each).
// ---------------------------------------------------------------------------
__global__ __launch_bounds__(256) void gemm_split(
    const __nv_bfloat16* __restrict__ Ahg, const __nv_bfloat16* __restrict__ Alg,
    const __nv_bfloat16* __restrict__ Bhg, const __nv_bfloat16* __restrict__ Blg,
    float* __restrict__ C, int M, int N, int K)
{
    extern __shared__ char dsmem[];
    const unsigned smem_u32 = (unsigned)__cvta_generic_to_shared(dsmem);

    const int tid  = threadIdx.x;
    const int wid  = tid >> 5;
    const int lane = tid & 31;
    const int wm = (wid >> 2) * 64;
    const int wn = (wid & 3) * 32;

    const int bm = blockIdx.y * 128;
    const int bn = blockIdx.x * 128;

    int crow[2], ccb[2];
    size_t aoff[2], boff[2];
    unsigned dsw[2];
#pragma unroll
    for (int i = 0; i < 2; i++) {
        int c = tid + i * 256;
        crow[i] = c >> 2;
        ccb[i]  = (c & 3) * 16;
        aoff[i] = (size_t)(bm + crow[i]) * K * 2 + ccb[i];
        boff[i] = (size_t)(bn + crow[i]) * K * 2 + ccb[i];
        dsw[i]  = swz(crow[i], ccb[i]);
    }
    const char* Ahc = (const char*)Ahg;
    const char* Alc = (const char*)Alg;
    const char* Bhc = (const char*)Bhg;
    const char* Blc = (const char*)Blg;

    auto issue_stage = [&](int stg, int k0) {
        unsigned sb = smem_u32 + (unsigned)stg * 32768u;
        size_t kb = (size_t)k0 * 2;
#pragma unroll
        for (int i = 0; i < 2; i++) {
            unsigned d = sb + dsw[i];
            CP16(d,          Ahc + aoff[i] + kb);
            CP16(d + 8192u,  Alc + aoff[i] + kb);
            CP16(d + 16384u, Bhc + boff[i] + kb);
            CP16(d + 24576u, Blc + boff[i] + kb);
        }
        CP_COMMIT();
    };

    float acc[4][4][4];
#pragma unroll
    for (int i = 0; i < 4; i++)
#pragma unroll
        for (int j = 0; j < 4; j++)
#pragma unroll
            for (int r = 0; r < 4; r++) acc[i][j][r] = 0.0f;

    const int lt = lane >> 3, lr = lane & 7;
    unsigned a_base[4], b_base[2];
#pragma unroll
    for (int mf = 0; mf < 4; mf++) {
        int m = wm + mf * 16 + (lt & 1) * 8 + lr;
        a_base[mf] = swz(m, (lt >> 1) * 16);
    }
#pragma unroll
    for (int np = 0; np < 2; np++) {
        int n = wn + np * 16 + (lt >> 1) * 8 + lr;
        b_base[np] = swz(n, (lt & 1) * 16);
    }

    const int nk = K / 32;
    issue_stage(0, 0);
    issue_stage(1, 32);
    issue_stage(2, 64);

    int cur = 0, nxt = 3;
    for (int kt = 0; kt < nk; kt++) {
        if (kt + 3 < nk) { CP_WAIT2(); } else { CP_WAIT0(); }
        __syncthreads();
        if (kt + 3 < nk) issue_stage(nxt, (kt + 3) * 32);

        const unsigned st = smem_u32 + (unsigned)cur * 32768u;
        const unsigned sAh = st, sAl = st + 8192u, sBh = st + 16384u, sBl = st + 24576u;

#pragma unroll
        for (int kk = 0; kk < 2; kk++) {
            const unsigned kb = kk * 32;   // XOR advance (bit 5 within swizzle field)
            unsigned ah[4][4], al[4][4];
#pragma unroll
            for (int mf = 0; mf < 4; mf++) {
                ldsm4(ah[mf][0], ah[mf][1], ah[mf][2], ah[mf][3], sAh + (a_base[mf] ^ kb));
                ldsm4(al[mf][0], al[mf][1], al[mf][2], al[mf][3], sAl + (a_base[mf] ^ kb));
            }
            unsigned bhf[4][2], blf[4][2];
#pragma unroll
            for (int np = 0; np < 2; np++) {
                ldsm4(bhf[2 * np][0], bhf[2 * np][1], bhf[2 * np + 1][0], bhf[2 * np + 1][1],
                      sBh + (b_base[np] ^ kb));
                ldsm4(blf[2 * np][0], blf[2 * np][1], blf[2 * np + 1][0], blf[2 * np + 1][1],
                      sBl + (b_base[np] ^ kb));
            }
            // Pass 1: hh
#pragma unroll
            for (int mf = 0; mf < 4; mf++)
#pragma unroll
                for (int nf = 0; nf < 4; nf++)
                    mma_bf16(acc[mf][nf], ah[mf][0], ah[mf][1], ah[mf][2], ah[mf][3],
                             bhf[nf][0], bhf[nf][1]);
            // Pass 2: hl
#pragma unroll
            for (int mf = 0; mf < 4; mf++)
#pragma unroll
                for (int nf = 0; nf < 4; nf++)
                    mma_bf16(acc[mf][nf], ah[mf][0], ah[mf][1], ah[mf][2], ah[mf][3],
                             blf[nf][0], blf[nf][1]);
            // Pass 3: lh
#pragma unroll
            for (int mf = 0; mf < 4; mf++)
#pragma unroll
                for (int nf = 0; nf < 4; nf++)
                    mma_bf16(acc[mf][nf], al[mf][0], al[mf][1], al[mf][2], al[mf][3],
                             bhf[nf][0], bhf[nf][1]);
        }
        cur = (cur + 1) & 3;
        nxt = (nxt + 1) & 3;
    }

    const int g = lane >> 2, th = lane & 3;
#pragma unroll
    for (int mf = 0; mf < 4; mf++) {
#pragma unroll
        for (int nf = 0; nf < 4; nf++) {
            int row = bm + wm + mf * 16 + g;
            int col = bn + wn + nf * 8 + 2 * th;
            *(float2*)(C + (size_t)row * N + col) =
                make_float2(acc[mf][nf][0], acc[mf][nf][1]);
            *(float2*)(C + (size_t)(row + 8) * N + col) =
                make_float2(acc[mf][nf][2], acc[mf][nf][3]);
        }
    }
}

// ---------------------------------------------------------------------------
// Phase 1: per-chunk sums of Tk_p(xk)*v per (b,h,chunk,d), plus chunk totals
// ---------------------------------------------------------------------------
__global__ __launch_bounds__(64) void chunk_kernel()
{
    const int blk = blockIdx.x;                 // b*512 + h*32 + c
    const int c = blk & 31, h = (blk >> 5) & 15, b = blk >> 9;
    const int d = threadIdx.x;

    const float* base = g_qkv + ((size_t)(b * S_LEN + c * CHS)) * (3 * DMODEL)
                        + DMODEL + h * DH + d;
    float kv[5] = {0, 0, 0, 0, 0};
    float rk[5] = {0, 0, 0, 0, 0};
#pragma unroll 4
    for (int s = 0; s < CHS; s++) {
        float kval = base[(size_t)s * (3 * DMODEL)];
        float vval = base[(size_t)s * (3 * DMODEL) + DMODEL];
        float t[5];
        cheb5(clampx(kval * 0.125f), t);
#pragma unroll
        for (int p = 0; p < 5; p++) { kv[p] += t[p] * vval; rk[p] += t[p]; }
    }
    const int bh = b * H_NUM + h;
#pragma unroll
    for (int p = 0; p < 5; p++)
        g_ckv[(((size_t)bh * 5 + p) * NCH + c) * DH + d] = kv[p];

    __shared__ float wred[5][2];
    const int lane = d & 31, w = d >> 5;
#pragma unroll
    for (int p = 0; p < 5; p++) {
        float v = rk[p];
#pragma unroll
        for (int o = 16; o > 0; o >>= 1) v += __shfl_down_sync(0xffffffffu, v, o);
        if (lane == 0) wred[p][w] = v;
    }
    __syncthreads();
    if (d == 0) {
#pragma unroll
        for (int p = 0; p < 5; p++)
            g_crk[((size_t)bh * 5 + p) * NCH + c] = wred[p][0] + wred[p][1];
    }
}

// ---------------------------------------------------------------------------
// Phase 2: block-parallel exclusive prefix over chunks.
// One block per bhp (=bh*5+p): 160 blocks x 1024 threads.
// ---------------------------------------------------------------------------
__global__ __launch_bounds__(1024) void prefix_kernel()
{
    const int bhp = blockIdx.x;          // 0..159
    const int tid = threadIdx.x;
    const int c  = tid >> 5;             // 0..31
    const int d0 = tid & 31;             // handles d0 and d0+32

    __shared__ float sm[2][NCH * DH];    // 2 x 8KB double buffer

    const size_t base = (size_t)bhp * NCH * DH;
    sm[0][c * DH + d0]      = g_ckv[base + c * DH + d0];
    sm[0][c * DH + d0 + 32] = g_ckv[base + c * DH + d0 + 32];
    __syncthreads();

    int src = 0;
#pragma unroll
    for (int st = 1; st < NCH; st <<= 1) {
        const int dst = src ^ 1;
        float v0 = sm[src][c * DH + d0];
        float v1 = sm[src][c * DH + d0 + 32];
        if (c >= st) {
            v0 += sm[src][(c - st) * DH + d0];
            v1 += sm[src][(c - st) * DH + d0 + 32];
        }
        sm[dst][c * DH + d0]      = v0;
        sm[dst][c * DH + d0 + 32] = v1;
        __syncthreads();
        src = dst;
    }

    float e0 = (c == 0) ? 0.0f : sm[src][(c - 1) * DH + d0];
    float e1 = (c == 0) ? 0.0f : sm[src][(c - 1) * DH + d0 + 32];
    g_ckv[base + c * DH + d0]      = e0;
    g_ckv[base + c * DH + d0 + 32] = e1;

    if (tid < 32) {
        const size_t rb = (size_t)bhp * NCH;
        float v = g_crk[rb + tid];
        float inc = v;
#pragma unroll
        for (int o = 1; o < 32; o <<= 1) {
            float t = __shfl_up_sync(0xffffffffu, inc, o);
            if (tid >= o) inc += t;
        }
        g_crk[rb + tid] = inc - v;
    }
}

// ---------------------------------------------------------------------------
// Phase 3 (fused den+final): one block per (b,h,chunk); 64 threads.
// ---------------------------------------------------------------------------
__global__ __launch_bounds__(64) void den_final_kernel(Betas bt)
{
    const int blk = blockIdx.x;
    const int c = blk & 31, h = (blk >> 5) & 15, b = blk >> 9;
    const int bh = b * H_NUM + h;

    __shared__ float part[10][32];
    __shared__ float sden[CHS];

    // ---- Phase A: den for s = c*CHS + sl, sl = 0..31 ----
    {
        const int sl = threadIdx.x & 31;
        const int w  = threadIdx.x >> 5;
        const int s = c * CHS + sl;
        const float* row = g_qkv + ((size_t)(b * S_LEN + s)) * (3 * DMODEL) + h * DH + w * 32;

        float Aq[5] = {0, 0, 0, 0, 0};
        float Rk[5] = {0, 0, 0, 0, 0};
#pragma unroll
        for (int d4 = 0; d4 < 32; d4 += 4) {
            float4 q4 = *(const float4*)(row + d4);
            float4 k4 = *(const float4*)(row + DMODEL + d4);
            const float qa[4] = {q4.x, q4.y, q4.z, q4.w};
            const float ka[4] = {k4.x, k4.y, k4.z, k4.w};
#pragma unroll
            for (int j = 0; j < 4; j++) {
                float tq[5], tk[5];
                cheb5(clampx(qa[j] * 0.125f), tq);
                cheb5(clampx(ka[j] * 0.125f), tk);
#pragma unroll
                for (int p = 0; p < 5; p++) { Aq[p] += tq[p]; Rk[p] += tk[p]; }
            }
        }

        if (w == 1) {
#pragma unroll
            for (int p = 0; p < 5; p++) { part[p][sl] = Aq[p]; part[5 + p][sl] = Rk[p]; }
        }
        __syncthreads();
        if (w == 0) {
#pragma unroll
            for (int p = 0; p < 5; p++) { Aq[p] += part[p][sl]; Rk[p] += part[5 + p][sl]; }

            float dsum = 0.0f;
#pragma unroll
            for (int p = 0; p < 5; p++) {
                float v = Rk[p];
#pragma unroll
                for (int o = 1; o < 32; o <<= 1) {
                    float t = __shfl_up_sync(0xffffffffu, v, o);
                    if (sl >= o) v += t;
                }
                float C = v + g_crk[((size_t)bh * 5 + p) * NCH + c];
                dsum += bt.b[p] * Aq[p] * C;
            }
            sden[sl] = dsum;
        }
        __syncthreads();
    }

    // ---- Phase B: rescan + output ----
    const int d = threadIdx.x;
    float kv[5];
#pragma unroll
    for (int p = 0; p < 5; p++)
        kv[p] = g_ckv[(((size_t)bh * 5 + p) * NCH + c) * DH + d];

    const float* base = g_qkv + ((size_t)(b * S_LEN + c * CHS)) * (3 * DMODEL) + h * DH + d;
    const size_t obase = ((size_t)(b * S_LEN + c * CHS)) * DMODEL + h * DH + d;

#pragma unroll 4
    for (int s = 0; s < CHS; s++) {
        const float* r = base + (size_t)s * (3 * DMODEL);
        float qv = r[0];
        float kval = r[DMODEL];
        float vval = r[2 * DMODEL];

        float tk[5];
        cheb5(clampx(kval * 0.125f), tk);
#pragma unroll
        for (int p = 0; p < 5; p++) kv[p] += tk[p] * vval;

        float tq[5];
        cheb5(clampx(qv * 0.125f), tq);
        float num = 0.0f;
#pragma unroll
        for (int p = 0; p < 5; p++) num += bt.b[p] * tq[p] * kv[p];

        float res = num / (sden[s] + 1e-7f);
        __nv_bfloat16 hi = __float2bfloat16(res);
        size_t idx = obase + (size_t)s * DMODEL;
        g_ath[idx] = hi;
        g_atl[idx] = __float2bfloat16(res - __bfloat162float(hi));
    }
}

// ---------------------------------------------------------------------------
extern "C" void kernel_launch(void* const* d_in, const int* in_sizes, int n_in,
                              void* d_out, int out_size)
{
    const float* x     = (const float*)d_in[0];   // (2,1024,1024)
    const float* W_in  = (const float*)d_in[1];   // (3072,1024)
    const float* W_out = (const float*)d_in[2];   // (1024,1024)
    float* out = (float*)d_out;                   // (2,1024,1024)

    float* qkv;
    cudaGetSymbolAddress((void**)&qkv, g_qkv);
    __nv_bfloat16 *xh, *xl, *wih, *wil, *woh, *wol, *ath, *atl;
    cudaGetSymbolAddress((void**)&xh,  g_xh);
    cudaGetSymbolAddress((void**)&xl,  g_xl);
    cudaGetSymbolAddress((void**)&wih, g_wih);
    cudaGetSymbolAddress((void**)&wil, g_wil);
    cudaGetSymbolAddress((void**)&woh, g_woh);
    cudaGetSymbolAddress((void**)&wol, g_wol);
    cudaGetSymbolAddress((void**)&ath, g_ath);
    cudaGetSymbolAddress((void**)&atl, g_atl);

    // beta[p] = tail[p+1] / sum(tail[1..5])
    double alpha[6], tail[7];
    tail[6] = 0.0;
    for (int j = 5; j >= 0; j--) {
        alpha[j] = pow((double)(j + 1), -1.5);
        tail[j] = tail[j + 1] + alpha[j];
    }
    double bsum = tail[1] + tail[2] + tail[3] + tail[4] + tail[5];
    Betas bt;
    for (int p = 0; p < 5; p++) bt.b[p] = (float)(tail[p + 1] / bsum);

    const int M = BATCH * S_LEN;           // 2048
    const int nx = M * DMODEL;             // 2M
    const int nw1 = 3 * DMODEL * DMODEL;   // 3M
    const int nw2 = DMODEL * DMODEL;       // 1M

    cudaFuncSetAttribute(gemm_split, cudaFuncAttributeMaxDynamicSharedMemorySize, 131072);

    // Launches 1-3: splits (also places gemm_split at launch #4 for the profiler)
    split_one<<<nx  / 4 / 256, 256>>>(x,     xh,  xl,  nx);
    split_one<<<nw1 / 4 / 256, 256>>>(W_in,  wih, wil, nw1);
    split_one<<<nw2 / 4 / 256, 256>>>(W_out, woh, wol, nw2);
    gemm_split<<<dim3(3 * DMODEL / 128, M / 128), 256, 131072>>>(
        xh, xl, wih, wil, qkv, M, 3 * DMODEL, DMODEL);
    chunk_kernel<<<BATCH * H_NUM * NCH, 64>>>();
    prefix_kernel<<<BATCH * H_NUM * 5, 1024>>>();
    den_final_kernel<<<BATCH * H_NUM * NCH, 64>>>(bt);
    gemm_split<<<dim3(DMODEL / 128, M / 128), 256, 131072>>>(
        ath, atl, woh, wol, out, M, DMODEL, DMODEL);
}

// round 14
// speedup vs baseline: 1.0837x; 1.0837x over previous
#include <cuda_runtime.h>
#include <cuda_bf16.h>
#include <cstdint>
#include <cmath>

// Problem constants
#define S_LEN   1024
#define DMODEL  1024
#define H_NUM   16
#define DH      64
#define BATCH   2
#define NCH     32     // chunks along S
#define CHS     32     // chunk length (S_LEN / NCH)

// Scratch (static device globals; no allocation allowed)
__device__ float g_qkv[(size_t)BATCH * S_LEN * 3 * DMODEL];   // 25.2 MB
__device__ float g_ckv[BATCH * H_NUM * 5 * NCH * DH];         // kv chunk sums -> exclusive prefix
__device__ float g_crk[BATCH * H_NUM * 5 * NCH];              // rk chunk sums -> exclusive prefix

// bf16 hi/lo split operands
__device__ __nv_bfloat16 g_xh[(size_t)BATCH * S_LEN * DMODEL];
__device__ __nv_bfloat16 g_xl[(size_t)BATCH * S_LEN * DMODEL];
__device__ __nv_bfloat16 g_wih[(size_t)3 * DMODEL * DMODEL];
__device__ __nv_bfloat16 g_wil[(size_t)3 * DMODEL * DMODEL];
__device__ __nv_bfloat16 g_woh[(size_t)DMODEL * DMODEL];
__device__ __nv_bfloat16 g_wol[(size_t)DMODEL * DMODEL];
__device__ __nv_bfloat16 g_ath[(size_t)BATCH * S_LEN * DMODEL];
__device__ __nv_bfloat16 g_atl[(size_t)BATCH * S_LEN * DMODEL];

struct Betas { float b[5]; };

__device__ __forceinline__ float clampx(float x) {
    return fminf(fmaxf(x, -1.0f + 1e-6f), 1.0f - 1e-6f);
}

__device__ __forceinline__ void cheb5(float x, float t[5]) {
    float x2 = x + x;
    float t1 = x;
    float t2 = x2 * t1 - 1.0f;
    float t3 = x2 * t2 - t1;
    float t4 = x2 * t3 - t2;
    float t5 = x2 * t4 - t3;
    t[0] = t1; t[1] = t2; t[2] = t3; t[3] = t4; t[4] = t5;
}

__device__ __forceinline__ unsigned pack2(__nv_bfloat16 a, __nv_bfloat16 b) {
    __nv_bfloat162 t(a, b);
    return *reinterpret_cast<unsigned*>(&t);
}

__device__ __forceinline__ void ldsm4(unsigned& r0, unsigned& r1, unsigned& r2, unsigned& r3,
                                      unsigned addr) {
    asm volatile("ldmatrix.sync.aligned.m8n8.x4.shared.b16 {%0,%1,%2,%3}, [%4];"
                 : "=r"(r0), "=r"(r1), "=r"(r2), "=r"(r3) : "r"(addr));
}

__device__ __forceinline__ void mma_bf16(float c[4],
                                         unsigned a0, unsigned a1, unsigned a2, unsigned a3,
                                         unsigned b0, unsigned b1) {
    asm volatile(
        "mma.sync.aligned.m16n8k16.row.col.f32.bf16.bf16.f32 "
        "{%0,%1,%2,%3}, {%4,%5,%6,%7}, {%8,%9}, {%0,%1,%2,%3};"
        : "+f"(c[0]), "+f"(c[1]), "+f"(c[2]), "+f"(c[3])
        : "r"(a0), "r"(a1), "r"(a2), "r"(a3), "r"(b0), "r"(b1));
}

#define CP16(dst, src) \
    asm volatile("cp.async.cg.shared.global [%0], [%1], 16;" :: "r"(dst), "l"(src))
#define CP_COMMIT() asm volatile("cp.async.commit_group;")
#define CP_WAIT1()  asm volatile("cp.async.wait_group 1;")
#define CP_WAIT0()  asm volatile("cp.async.wait_group 0;")

// swizzled byte offset inside a 128x32 bf16 tile (64B rows).
__device__ __forceinline__ unsigned swz(int m, int cbyte) {
    return (unsigned)((m << 6) + (cbyte ^ (((m >> 1) & 3) << 4)));
}

// ---------------------------------------------------------------------------
// split_one: f32 -> bf16 hi + bf16 lo residual, one tensor per launch
// ---------------------------------------------------------------------------
__global__ __launch_bounds__(256) void split_one(
    const float* __restrict__ src, __nv_bfloat16* __restrict__ hi,
    __nv_bfloat16* __restrict__ lo, int n)
{
    int i = (blockIdx.x * blockDim.x + threadIdx.x) * 4;
    if (i >= n) return;

    float4 v = *(const float4*)(src + i);
    __nv_bfloat16 h0 = __float2bfloat16(v.x), h1 = __float2bfloat16(v.y);
    __nv_bfloat16 h2 = __float2bfloat16(v.z), h3 = __float2bfloat16(v.w);
    __nv_bfloat16 l0 = __float2bfloat16(v.x - __bfloat162float(h0));
    __nv_bfloat16 l1 = __float2bfloat16(v.y - __bfloat162float(h1));
    __nv_bfloat16 l2 = __float2bfloat16(v.z - __bfloat162float(h2));
    __nv_bfloat16 l3 = __float2bfloat16(v.w - __bfloat162float(h3));
    *(uint2*)(hi + i) = make_uint2(pack2(h0, h1), pack2(h2, h3));
    *(uint2*)(lo + i) = make_uint2(pack2(l0, l1), pack2(l2, l3));
}

// ---------------------------------------------------------------------------
// bf16x3 GEMM, pre-split operands, 3-stage cp.async pipeline (1 sync/tile):
//   C[M,N] = (Ah+Al)[M,K] @ (Bh+Bl)[N,K]^T  (drop Al*Bl)
// BM=BN=128, BK=32, 256 threads (8 warps 2x4), warp tile 64x32.
// Dynamic smem: 3 stages x 32KB -> 96KB; 2 CTAs/SM resident (regs=128 fits 2).
// ---------------------------------------------------------------------------
__global__ __launch_bounds__(256) void gemm_split(
    const __nv_bfloat16* __restrict__ Ahg, const __nv_bfloat16* __restrict__ Alg,
    const __nv_bfloat16* __restrict__ Bhg, const __nv_bfloat16* __restrict__ Blg,
    float* __restrict__ C, int M, int N, int K)
{
    extern __shared__ char dsmem[];
    const unsigned smem_u32 = (unsigned)__cvta_generic_to_shared(dsmem);

    const int tid  = threadIdx.x;
    const int wid  = tid >> 5;
    const int lane = tid & 31;
    const int wm = (wid >> 2) * 64;
    const int wn = (wid & 3) * 32;

    const int bm = blockIdx.y * 128;
    const int bn = blockIdx.x * 128;

    int crow[2], ccb[2];
    size_t aoff[2], boff[2];
    unsigned dsw[2];
#pragma unroll
    for (int i = 0; i < 2; i++) {
        int c = tid + i * 256;
        crow[i] = c >> 2;
        ccb[i]  = (c & 3) * 16;
        aoff[i] = (size_t)(bm + crow[i]) * K * 2 + ccb[i];
        boff[i] = (size_t)(bn + crow[i]) * K * 2 + ccb[i];
        dsw[i]  = swz(crow[i], ccb[i]);
    }
    const char* Ahc = (const char*)Ahg;
    const char* Alc = (const char*)Alg;
    const char* Bhc = (const char*)Bhg;
    const char* Blc = (const char*)Blg;

    auto issue_stage = [&](int stg, int k0) {
        unsigned sb = smem_u32 + (unsigned)stg * 32768u;
        size_t kb = (size_t)k0 * 2;
#pragma unroll
        for (int i = 0; i < 2; i++) {
            unsigned d = sb + dsw[i];
            CP16(d,          Ahc + aoff[i] + kb);
            CP16(d + 8192u,  Alc + aoff[i] + kb);
            CP16(d + 16384u, Bhc + boff[i] + kb);
            CP16(d + 24576u, Blc + boff[i] + kb);
        }
        CP_COMMIT();
    };

    float acc[4][4][4];
#pragma unroll
    for (int i = 0; i < 4; i++)
#pragma unroll
        for (int j = 0; j < 4; j++)
#pragma unroll
            for (int r = 0; r < 4; r++) acc[i][j][r] = 0.0f;

    const int lt = lane >> 3, lr = lane & 7;
    unsigned a_base[4], b_base[2];
#pragma unroll
    for (int mf = 0; mf < 4; mf++) {
        int m = wm + mf * 16 + (lt & 1) * 8 + lr;
        a_base[mf] = swz(m, (lt >> 1) * 16);
    }
#pragma unroll
    for (int np = 0; np < 2; np++) {
        int n = wn + np * 16 + (lt >> 1) * 8 + lr;
        b_base[np] = swz(n, (lt & 1) * 16);
    }

    const int nk = K / 32;
    issue_stage(0, 0);
    issue_stage(1, 32);

    int cur = 0, nxt = 2;
    for (int kt = 0; kt < nk; kt++) {
        if (kt + 2 < nk) { CP_WAIT1(); } else { CP_WAIT0(); }
        __syncthreads();
        if (kt + 2 < nk) issue_stage(nxt, (kt + 2) * 32);

        const unsigned st = smem_u32 + (unsigned)cur * 32768u;
        const unsigned sAh = st, sAl = st + 8192u, sBh = st + 16384u, sBl = st + 24576u;

#pragma unroll
        for (int kk = 0; kk < 2; kk++) {
            const unsigned kb = kk * 32;   // XOR advance (bit 5 within swizzle field)
            unsigned ah[4][4], al[4][4];
#pragma unroll
            for (int mf = 0; mf < 4; mf++) {
                ldsm4(ah[mf][0], ah[mf][1], ah[mf][2], ah[mf][3], sAh + (a_base[mf] ^ kb));
                ldsm4(al[mf][0], al[mf][1], al[mf][2], al[mf][3], sAl + (a_base[mf] ^ kb));
            }
            unsigned bhf[4][2], blf[4][2];
#pragma unroll
            for (int np = 0; np < 2; np++) {
                ldsm4(bhf[2 * np][0], bhf[2 * np][1], bhf[2 * np + 1][0], bhf[2 * np + 1][1],
                      sBh + (b_base[np] ^ kb));
                ldsm4(blf[2 * np][0], blf[2 * np][1], blf[2 * np + 1][0], blf[2 * np + 1][1],
                      sBl + (b_base[np] ^ kb));
            }
            // Pass 1: hh
#pragma unroll
            for (int mf = 0; mf < 4; mf++)
#pragma unroll
                for (int nf = 0; nf < 4; nf++)
                    mma_bf16(acc[mf][nf], ah[mf][0], ah[mf][1], ah[mf][2], ah[mf][3],
                             bhf[nf][0], bhf[nf][1]);
            // Pass 2: hl
#pragma unroll
            for (int mf = 0; mf < 4; mf++)
#pragma unroll
                for (int nf = 0; nf < 4; nf++)
                    mma_bf16(acc[mf][nf], ah[mf][0], ah[mf][1], ah[mf][2], ah[mf][3],
                             blf[nf][0], blf[nf][1]);
            // Pass 3: lh
#pragma unroll
            for (int mf = 0; mf < 4; mf++)
#pragma unroll
                for (int nf = 0; nf < 4; nf++)
                    mma_bf16(acc[mf][nf], al[mf][0], al[mf][1], al[mf][2], al[mf][3],
                             bhf[nf][0], bhf[nf][1]);
        }
        cur = (cur + 1 == 3) ? 0 : cur + 1;
        nxt = (nxt + 1 == 3) ? 0 : nxt + 1;
    }

    const int g = lane >> 2, th = lane & 3;
#pragma unroll
    for (int mf = 0; mf < 4; mf++) {
#pragma unroll
        for (int nf = 0; nf < 4; nf++) {
            int row = bm + wm + mf * 16 + g;
            int col = bn + wn + nf * 8 + 2 * th;
            *(float2*)(C + (size_t)row * N + col) =
                make_float2(acc[mf][nf][0], acc[mf][nf][1]);
            *(float2*)(C + (size_t)(row + 8) * N + col) =
                make_float2(acc[mf][nf][2], acc[mf][nf][3]);
        }
    }
}

// ---------------------------------------------------------------------------
// Phase 1: per-chunk sums of Tk_p(xk)*v per (b,h,chunk,d), plus chunk totals.
// 128 threads: two warps split the s range (16 steps each) -> half the serial
// load chain, double resident warps; combine halves via smem.
// ---------------------------------------------------------------------------
__global__ __launch_bounds__(128) void chunk_kernel()
{
    const int blk = blockIdx.x;                 // b*512 + h*32 + c
    const int c = blk & 31, h = (blk >> 5) & 15, b = blk >> 9;
    const int d    = threadIdx.x & 63;
    const int half = threadIdx.x >> 6;          // s-half (0 or 1)

    const float* base = g_qkv + ((size_t)(b * S_LEN + c * CHS + half * 16)) * (3 * DMODEL)
                        + DMODEL + h * DH + d;
    float kv[5] = {0, 0, 0, 0, 0};
    float rk[5] = {0, 0, 0, 0, 0};
#pragma unroll 4
    for (int s = 0; s < 16; s++) {
        float kval = base[(size_t)s * (3 * DMODEL)];
        float vval = base[(size_t)s * (3 * DMODEL) + DMODEL];
        float t[5];
        cheb5(clampx(kval * 0.125f), t);
#pragma unroll
        for (int p = 0; p < 5; p++) { kv[p] += t[p] * vval; rk[p] += t[p]; }
    }

    __shared__ float kpart[5][64];
    if (half == 1) {
#pragma unroll
        for (int p = 0; p < 5; p++) kpart[p][d] = kv[p];
    }
    __syncthreads();
    const int bh = b * H_NUM + h;
    if (half == 0) {
#pragma unroll
        for (int p = 0; p < 5; p++) {
            kv[p] += kpart[p][d];
            g_ckv[(((size_t)bh * 5 + p) * NCH + c) * DH + d] = kv[p];
        }
    }

    // block-reduce rk over all 128 threads (4 warps)
    __shared__ float wred[5][4];
    const int lane = threadIdx.x & 31, w = threadIdx.x >> 5;
#pragma unroll
    for (int p = 0; p < 5; p++) {
        float v = rk[p];
#pragma unroll
        for (int o = 16; o > 0; o >>= 1) v += __shfl_down_sync(0xffffffffu, v, o);
        if (lane == 0) wred[p][w] = v;
    }
    __syncthreads();
    if (threadIdx.x == 0) {
#pragma unroll
        for (int p = 0; p < 5; p++)
            g_crk[((size_t)bh * 5 + p) * NCH + c] =
                (wred[p][0] + wred[p][1]) + (wred[p][2] + wred[p][3]);
    }
}

// ---------------------------------------------------------------------------
// Phase 2: block-parallel exclusive prefix over chunks.
// One block per bhp (=bh*5+p): 160 blocks x 1024 threads.
// ---------------------------------------------------------------------------
__global__ __launch_bounds__(1024) void prefix_kernel()
{
    const int bhp = blockIdx.x;          // 0..159
    const int tid = threadIdx.x;
    const int c  = tid >> 5;             // 0..31
    const int d0 = tid & 31;             // handles d0 and d0+32

    __shared__ float sm[2][NCH * DH];    // 2 x 8KB double buffer

    const size_t base = (size_t)bhp * NCH * DH;
    sm[0][c * DH + d0]      = g_ckv[base + c * DH + d0];
    sm[0][c * DH + d0 + 32] = g_ckv[base + c * DH + d0 + 32];
    __syncthreads();

    int src = 0;
#pragma unroll
    for (int st = 1; st < NCH; st <<= 1) {
        const int dst = src ^ 1;
        float v0 = sm[src][c * DH + d0];
        float v1 = sm[src][c * DH + d0 + 32];
        if (c >= st) {
            v0 += sm[src][(c - st) * DH + d0];
            v1 += sm[src][(c - st) * DH + d0 + 32];
        }
        sm[dst][c * DH + d0]      = v0;
        sm[dst][c * DH + d0 + 32] = v1;
        __syncthreads();
        src = dst;
    }

    float e0 = (c == 0) ? 0.0f : sm[src][(c - 1) * DH + d0];
    float e1 = (c == 0) ? 0.0f : sm[src][(c - 1) * DH + d0 + 32];
    g_ckv[base + c * DH + d0]      = e0;
    g_ckv[base + c * DH + d0 + 32] = e1;

    if (tid < 32) {
        const size_t rb = (size_t)bhp * NCH;
        float v = g_crk[rb + tid];
        float inc = v;
#pragma unroll
        for (int o = 1; o < 32; o <<= 1) {
            float t = __shfl_up_sync(0xffffffffu, inc, o);
            if (tid >= o) inc += t;
        }
        g_crk[rb + tid] = inc - v;
    }
}

// ---------------------------------------------------------------------------
// Phase 3 (fused den+final): one block per (b,h,chunk); 64 threads.
// ---------------------------------------------------------------------------
__global__ __launch_bounds__(64) void den_final_kernel(Betas bt)
{
    const int blk = blockIdx.x;
    const int c = blk & 31, h = (blk >> 5) & 15, b = blk >> 9;
    const int bh = b * H_NUM + h;

    __shared__ float part[10][32];
    __shared__ float sden[CHS];

    // ---- Phase A: den for s = c*CHS + sl, sl = 0..31 ----
    {
        const int sl = threadIdx.x & 31;
        const int w  = threadIdx.x >> 5;
        const int s = c * CHS + sl;
        const float* row = g_qkv + ((size_t)(b * S_LEN + s)) * (3 * DMODEL) + h * DH + w * 32;

        float Aq[5] = {0, 0, 0, 0, 0};
        float Rk[5] = {0, 0, 0, 0, 0};
#pragma unroll
        for (int d4 = 0; d4 < 32; d4 += 4) {
            float4 q4 = *(const float4*)(row + d4);
            float4 k4 = *(const float4*)(row + DMODEL + d4);
            const float qa[4] = {q4.x, q4.y, q4.z, q4.w};
            const float ka[4] = {k4.x, k4.y, k4.z, k4.w};
#pragma unroll
            for (int j = 0; j < 4; j++) {
                float tq[5], tk[5];
                cheb5(clampx(qa[j] * 0.125f), tq);
                cheb5(clampx(ka[j] * 0.125f), tk);
#pragma unroll
                for (int p = 0; p < 5; p++) { Aq[p] += tq[p]; Rk[p] += tk[p]; }
            }
        }

        if (w == 1) {
#pragma unroll
            for (int p = 0; p < 5; p++) { part[p][sl] = Aq[p]; part[5 + p][sl] = Rk[p]; }
        }
        __syncthreads();
        if (w == 0) {
#pragma unroll
            for (int p = 0; p < 5; p++) { Aq[p] += part[p][sl]; Rk[p] += part[5 + p][sl]; }

            float dsum = 0.0f;
#pragma unroll
            for (int p = 0; p < 5; p++) {
                float v = Rk[p];
#pragma unroll
                for (int o = 1; o < 32; o <<= 1) {
                    float t = __shfl_up_sync(0xffffffffu, v, o);
                    if (sl >= o) v += t;
                }
                float C = v + g_crk[((size_t)bh * 5 + p) * NCH + c];
                dsum += bt.b[p] * Aq[p] * C;
            }
            sden[sl] = dsum;
        }
        __syncthreads();
    }

    // ---- Phase B: rescan + output ----
    const int d = threadIdx.x;
    float kv[5];
#pragma unroll
    for (int p = 0; p < 5; p++)
        kv[p] = g_ckv[(((size_t)bh * 5 + p) * NCH + c) * DH + d];

    const float* base = g_qkv + ((size_t)(b * S_LEN + c * CHS)) * (3 * DMODEL) + h * DH + d;
    const size_t obase = ((size_t)(b * S_LEN + c * CHS)) * DMODEL + h * DH + d;

#pragma unroll 4
    for (int s = 0; s < CHS; s++) {
        const float* r = base + (size_t)s * (3 * DMODEL);
        float qv = r[0];
        float kval = r[DMODEL];
        float vval = r[2 * DMODEL];

        float tk[5];
        cheb5(clampx(kval * 0.125f), tk);
#pragma unroll
        for (int p = 0; p < 5; p++) kv[p] += tk[p] * vval;

        float tq[5];
        cheb5(clampx(qv * 0.125f), tq);
        float num = 0.0f;
#pragma unroll
        for (int p = 0; p < 5; p++) num += bt.b[p] * tq[p] * kv[p];

        float res = num / (sden[s] + 1e-7f);
        __nv_bfloat16 hi = __float2bfloat16(res);
        size_t idx = obase + (size_t)s * DMODEL;
        g_ath[idx] = hi;
        g_atl[idx] = __float2bfloat16(res - __bfloat162float(hi));
    }
}

// ---------------------------------------------------------------------------
extern "C" void kernel_launch(void* const* d_in, const int* in_sizes, int n_in,
                              void* d_out, int out_size)
{
    const float* x     = (const float*)d_in[0];   // (2,1024,1024)
    const float* W_in  = (const float*)d_in[1];   // (3072,1024)
    const float* W_out = (const float*)d_in[2];   // (1024,1024)
    float* out = (float*)d_out;                   // (2,1024,1024)

    float* qkv;
    cudaGetSymbolAddress((void**)&qkv, g_qkv);
    __nv_bfloat16 *xh, *xl, *wih, *wil, *woh, *wol, *ath, *atl;
    cudaGetSymbolAddress((void**)&xh,  g_xh);
    cudaGetSymbolAddress((void**)&xl,  g_xl);
    cudaGetSymbolAddress((void**)&wih, g_wih);
    cudaGetSymbolAddress((void**)&wil, g_wil);
    cudaGetSymbolAddress((void**)&woh, g_woh);
    cudaGetSymbolAddress((void**)&wol, g_wol);
    cudaGetSymbolAddress((void**)&ath, g_ath);
    cudaGetSymbolAddress((void**)&atl, g_atl);

    // beta[p] = tail[p+1] / sum(tail[1..5])
    double alpha[6], tail[7];
    tail[6] = 0.0;
    for (int j = 5; j >= 0; j--) {
        alpha[j] = pow((double)(j + 1), -1.5);
        tail[j] = tail[j + 1] + alpha[j];
    }
    double bsum = tail[1] + tail[2] + tail[3] + tail[4] + tail[5];
    Betas bt;
    for (int p = 0; p < 5; p++) bt.b[p] = (float)(tail[p + 1] / bsum);

    const int M = BATCH * S_LEN;           // 2048
    const int nx = M * DMODEL;             // 2M
    const int nw1 = 3 * DMODEL * DMODEL;   // 3M
    const int nw2 = DMODEL * DMODEL;       // 1M

    cudaFuncSetAttribute(gemm_split, cudaFuncAttributeMaxDynamicSharedMemorySize, 98304);

    // Launches 1-3: splits (keeps gemm_split at launch #4 for the profiler)
    split_one<<<nx  / 4 / 256, 256>>>(x,     xh,  xl,  nx);
    split_one<<<nw1 / 4 / 256, 256>>>(W_in,  wih, wil, nw1);
    split_one<<<nw2 / 4 / 256, 256>>>(W_out, woh, wol, nw2);
    gemm_split<<<dim3(3 * DMODEL / 128, M / 128), 256, 98304>>>(
        xh, xl, wih, wil, qkv, M, 3 * DMODEL, DMODEL);
    chunk_kernel<<<BATCH * H_NUM * NCH, 128>>>();
    prefix_kernel<<<BATCH * H_NUM * 5, 1024>>>();
    den_final_kernel<<<BATCH * H_NUM * NCH, 64>>>(bt);
    gemm_split<<<dim3(DMODEL / 128, M / 128), 256, 98304>>>(
        ath, atl, woh, wol, out, M, DMODEL, DMODEL);
}

// round 15
// speedup vs baseline: 1.1163x; 1.0301x over previous
#include <cuda_runtime.h>
#include <cuda_bf16.h>
#include <cstdint>
#include <cmath>

// Problem constants
#define S_LEN   1024
#define DMODEL  1024
#define H_NUM   16
#define DH      64
#define BATCH   2
#define NCH     32     // chunks along S
#define CHS     32     // chunk length (S_LEN / NCH)

// Scratch (static device globals; no allocation allowed)
__device__ float g_qkv[(size_t)BATCH * S_LEN * 3 * DMODEL];   // 25.2 MB
__device__ float g_ckv[BATCH * H_NUM * 5 * NCH * DH];         // kv chunk sums -> exclusive prefix
__device__ float g_crk[BATCH * H_NUM * 5 * NCH];              // rk chunk sums -> exclusive prefix

// bf16 hi/lo split operands
__device__ __nv_bfloat16 g_xh[(size_t)BATCH * S_LEN * DMODEL];
__device__ __nv_bfloat16 g_xl[(size_t)BATCH * S_LEN * DMODEL];
__device__ __nv_bfloat16 g_wih[(size_t)3 * DMODEL * DMODEL];
__device__ __nv_bfloat16 g_wil[(size_t)3 * DMODEL * DMODEL];
__device__ __nv_bfloat16 g_woh[(size_t)DMODEL * DMODEL];
__device__ __nv_bfloat16 g_wol[(size_t)DMODEL * DMODEL];
__device__ __nv_bfloat16 g_ath[(size_t)BATCH * S_LEN * DMODEL];
__device__ __nv_bfloat16 g_atl[(size_t)BATCH * S_LEN * DMODEL];

struct Betas { float b[5]; };

__device__ __forceinline__ float clampx(float x) {
    return fminf(fmaxf(x, -1.0f + 1e-6f), 1.0f - 1e-6f);
}

__device__ __forceinline__ void cheb5(float x, float t[5]) {
    float x2 = x + x;
    float t1 = x;
    float t2 = x2 * t1 - 1.0f;
    float t3 = x2 * t2 - t1;
    float t4 = x2 * t3 - t2;
    float t5 = x2 * t4 - t3;
    t[0] = t1; t[1] = t2; t[2] = t3; t[3] = t4; t[4] = t5;
}

__device__ __forceinline__ unsigned pack2(__nv_bfloat16 a, __nv_bfloat16 b) {
    __nv_bfloat162 t(a, b);
    return *reinterpret_cast<unsigned*>(&t);
}

__device__ __forceinline__ void ldsm4(unsigned& r0, unsigned& r1, unsigned& r2, unsigned& r3,
                                      unsigned addr) {
    asm volatile("ldmatrix.sync.aligned.m8n8.x4.shared.b16 {%0,%1,%2,%3}, [%4];"
                 : "=r"(r0), "=r"(r1), "=r"(r2), "=r"(r3) : "r"(addr));
}

__device__ __forceinline__ void mma_bf16(float c[4],
                                         unsigned a0, unsigned a1, unsigned a2, unsigned a3,
                                         unsigned b0, unsigned b1) {
    asm volatile(
        "mma.sync.aligned.m16n8k16.row.col.f32.bf16.bf16.f32 "
        "{%0,%1,%2,%3}, {%4,%5,%6,%7}, {%8,%9}, {%0,%1,%2,%3};"
        : "+f"(c[0]), "+f"(c[1]), "+f"(c[2]), "+f"(c[3])
        : "r"(a0), "r"(a1), "r"(a2), "r"(a3), "r"(b0), "r"(b1));
}

#define CP16(dst, src) \
    asm volatile("cp.async.cg.shared.global [%0], [%1], 16;" :: "r"(dst), "l"(src))
#define CP_COMMIT() asm volatile("cp.async.commit_group;")
#define CP_WAIT1()  asm volatile("cp.async.wait_group 1;")
#define CP_WAIT0()  asm volatile("cp.async.wait_group 0;")

// swizzled byte offset inside a 128x32 bf16 tile (64B rows).
__device__ __forceinline__ unsigned swz(int m, int cbyte) {
    return (unsigned)((m << 6) + (cbyte ^ (((m >> 1) & 3) << 4)));
}

// ---------------------------------------------------------------------------
// split3: f32 -> bf16 hi + bf16 lo residual, three tensors in one launch
// ---------------------------------------------------------------------------
__global__ __launch_bounds__(256) void split3(
    const float* __restrict__ a, __nv_bfloat16* __restrict__ ah, __nv_bfloat16* __restrict__ al, int na,
    const float* __restrict__ b, __nv_bfloat16* __restrict__ bh, __nv_bfloat16* __restrict__ bl, int nb,
    const float* __restrict__ c, __nv_bfloat16* __restrict__ ch, __nv_bfloat16* __restrict__ cl, int nc)
{
    int i = (blockIdx.x * blockDim.x + threadIdx.x) * 4;
    const float* src; __nv_bfloat16 *hi, *lo; int off;
    if (i < na)           { src = a; hi = ah; lo = al; off = i; }
    else if (i < na + nb) { src = b; hi = bh; lo = bl; off = i - na; }
    else if (i < na + nb + nc) { src = c; hi = ch; lo = cl; off = i - na - nb; }
    else return;

    float4 v = *(const float4*)(src + off);
    __nv_bfloat16 h0 = __float2bfloat16(v.x), h1 = __float2bfloat16(v.y);
    __nv_bfloat16 h2 = __float2bfloat16(v.z), h3 = __float2bfloat16(v.w);
    __nv_bfloat16 l0 = __float2bfloat16(v.x - __bfloat162float(h0));
    __nv_bfloat16 l1 = __float2bfloat16(v.y - __bfloat162float(h1));
    __nv_bfloat16 l2 = __float2bfloat16(v.z - __bfloat162float(h2));
    __nv_bfloat16 l3 = __float2bfloat16(v.w - __bfloat162float(h3));
    *(uint2*)(hi + off) = make_uint2(pack2(h0, h1), pack2(h2, h3));
    *(uint2*)(lo + off) = make_uint2(pack2(l0, l1), pack2(l2, l3));
}

// ---------------------------------------------------------------------------
// bf16x3 GEMM, pre-split operands, 3-stage cp.async pipeline (1 sync/tile):
//   C[M,N] = (Ah+Al)[M,K] @ (Bh+Bl)[N,K]^T  (drop Al*Bl)
// BM=BN=128, BK=32, 256 threads (8 warps 2x4), warp tile 64x32.
// Dynamic smem: 3 stages x 32KB -> 96KB; 2 CTAs/SM resident (regs=128 fits 2).
// ---------------------------------------------------------------------------
__global__ __launch_bounds__(256) void gemm_split(
    const __nv_bfloat16* __restrict__ Ahg, const __nv_bfloat16* __restrict__ Alg,
    const __nv_bfloat16* __restrict__ Bhg, const __nv_bfloat16* __restrict__ Blg,
    float* __restrict__ C, int M, int N, int K)
{
    extern __shared__ char dsmem[];
    const unsigned smem_u32 = (unsigned)__cvta_generic_to_shared(dsmem);

    const int tid  = threadIdx.x;
    const int wid  = tid >> 5;
    const int lane = tid & 31;
    const int wm = (wid >> 2) * 64;
    const int wn = (wid & 3) * 32;

    const int bm = blockIdx.y * 128;
    const int bn = blockIdx.x * 128;

    int crow[2], ccb[2];
    size_t aoff[2], boff[2];
    unsigned dsw[2];
#pragma unroll
    for (int i = 0; i < 2; i++) {
        int c = tid + i * 256;
        crow[i] = c >> 2;
        ccb[i]  = (c & 3) * 16;
        aoff[i] = (size_t)(bm + crow[i]) * K * 2 + ccb[i];
        boff[i] = (size_t)(bn + crow[i]) * K * 2 + ccb[i];
        dsw[i]  = swz(crow[i], ccb[i]);
    }
    const char* Ahc = (const char*)Ahg;
    const char* Alc = (const char*)Alg;
    const char* Bhc = (const char*)Bhg;
    const char* Blc = (const char*)Blg;

    auto issue_stage = [&](int stg, int k0) {
        unsigned sb = smem_u32 + (unsigned)stg * 32768u;
        size_t kb = (size_t)k0 * 2;
#pragma unroll
        for (int i = 0; i < 2; i++) {
            unsigned d = sb + dsw[i];
            CP16(d,          Ahc + aoff[i] + kb);
            CP16(d + 8192u,  Alc + aoff[i] + kb);
            CP16(d + 16384u, Bhc + boff[i] + kb);
            CP16(d + 24576u, Blc + boff[i] + kb);
        }
        CP_COMMIT();
    };

    float acc[4][4][4];
#pragma unroll
    for (int i = 0; i < 4; i++)
#pragma unroll
        for (int j = 0; j < 4; j++)
#pragma unroll
            for (int r = 0; r < 4; r++) acc[i][j][r] = 0.0f;

    const int lt = lane >> 3, lr = lane & 7;
    unsigned a_base[4], b_base[2];
#pragma unroll
    for (int mf = 0; mf < 4; mf++) {
        int m = wm + mf * 16 + (lt & 1) * 8 + lr;
        a_base[mf] = swz(m, (lt >> 1) * 16);
    }
#pragma unroll
    for (int np = 0; np < 2; np++) {
        int n = wn + np * 16 + (lt >> 1) * 8 + lr;
        b_base[np] = swz(n, (lt & 1) * 16);
    }

    const int nk = K / 32;
    issue_stage(0, 0);
    issue_stage(1, 32);

    int cur = 0, nxt = 2;
    for (int kt = 0; kt < nk; kt++) {
        if (kt + 2 < nk) { CP_WAIT1(); } else { CP_WAIT0(); }
        __syncthreads();
        if (kt + 2 < nk) issue_stage(nxt, (kt + 2) * 32);

        const unsigned st = smem_u32 + (unsigned)cur * 32768u;
        const unsigned sAh = st, sAl = st + 8192u, sBh = st + 16384u, sBl = st + 24576u;

#pragma unroll
        for (int kk = 0; kk < 2; kk++) {
            const unsigned kb = kk * 32;   // XOR advance (bit 5 within swizzle field)
            unsigned ah[4][4], al[4][4];
#pragma unroll
            for (int mf = 0; mf < 4; mf++) {
                ldsm4(ah[mf][0], ah[mf][1], ah[mf][2], ah[mf][3], sAh + (a_base[mf] ^ kb));
                ldsm4(al[mf][0], al[mf][1], al[mf][2], al[mf][3], sAl + (a_base[mf] ^ kb));
            }
            unsigned bhf[4][2], blf[4][2];
#pragma unroll
            for (int np = 0; np < 2; np++) {
                ldsm4(bhf[2 * np][0], bhf[2 * np][1], bhf[2 * np + 1][0], bhf[2 * np + 1][1],
                      sBh + (b_base[np] ^ kb));
                ldsm4(blf[2 * np][0], blf[2 * np][1], blf[2 * np + 1][0], blf[2 * np + 1][1],
                      sBl + (b_base[np] ^ kb));
            }
            // Pass 1: hh
#pragma unroll
            for (int mf = 0; mf < 4; mf++)
#pragma unroll
                for (int nf = 0; nf < 4; nf++)
                    mma_bf16(acc[mf][nf], ah[mf][0], ah[mf][1], ah[mf][2], ah[mf][3],
                             bhf[nf][0], bhf[nf][1]);
            // Pass 2: hl
#pragma unroll
            for (int mf = 0; mf < 4; mf++)
#pragma unroll
                for (int nf = 0; nf < 4; nf++)
                    mma_bf16(acc[mf][nf], ah[mf][0], ah[mf][1], ah[mf][2], ah[mf][3],
                             blf[nf][0], blf[nf][1]);
            // Pass 3: lh
#pragma unroll
            for (int mf = 0; mf < 4; mf++)
#pragma unroll
                for (int nf = 0; nf < 4; nf++)
                    mma_bf16(acc[mf][nf], al[mf][0], al[mf][1], al[mf][2], al[mf][3],
                             bhf[nf][0], bhf[nf][1]);
        }
        cur = (cur + 1 == 3) ? 0 : cur + 1;
        nxt = (nxt + 1 == 3) ? 0 : nxt + 1;
    }

    const int g = lane >> 2, th = lane & 3;
#pragma unroll
    for (int mf = 0; mf < 4; mf++) {
#pragma unroll
        for (int nf = 0; nf < 4; nf++) {
            int row = bm + wm + mf * 16 + g;
            int col = bn + wn + nf * 8 + 2 * th;
            *(float2*)(C + (size_t)row * N + col) =
                make_float2(acc[mf][nf][0], acc[mf][nf][1]);
            *(float2*)(C + (size_t)(row + 8) * N + col) =
                make_float2(acc[mf][nf][2], acc[mf][nf][3]);
        }
    }
}

// ---------------------------------------------------------------------------
// Phase 1: per-chunk sums of Tk_p(xk)*v per (b,h,chunk,d), plus chunk totals.
// k/v staged into smem with coalesced float4 loads (full MLP), then the
// per-d accumulate loop runs from smem.
// ---------------------------------------------------------------------------
__global__ __launch_bounds__(64) void chunk_kernel()
{
    const int blk = blockIdx.x;                 // b*512 + h*32 + c
    const int c = blk & 31, h = (blk >> 5) & 15, b = blk >> 9;
    const int d = threadIdx.x;

    __shared__ float sk[CHS][DH];
    __shared__ float sv[CHS][DH];

    // cooperative stage: 512 float4 per stream, 64 threads -> 8 iters
    {
        const float* kb = g_qkv + ((size_t)(b * S_LEN + c * CHS)) * (3 * DMODEL)
                          + DMODEL + h * DH;
        for (int i = d; i < CHS * 16; i += 64) {
            int s = i >> 4, d4 = (i & 15) * 4;
            const float* row = kb + (size_t)s * (3 * DMODEL) + d4;
            *(float4*)&sk[s][d4] = *(const float4*)row;
            *(float4*)&sv[s][d4] = *(const float4*)(row + DMODEL);
        }
    }
    __syncthreads();

    float kv[5] = {0, 0, 0, 0, 0};
    float rk[5] = {0, 0, 0, 0, 0};
#pragma unroll 4
    for (int s = 0; s < CHS; s++) {
        float t[5];
        cheb5(clampx(sk[s][d] * 0.125f), t);
        float vval = sv[s][d];
#pragma unroll
        for (int p = 0; p < 5; p++) { kv[p] += t[p] * vval; rk[p] += t[p]; }
    }
    const int bh = b * H_NUM + h;
#pragma unroll
    for (int p = 0; p < 5; p++)
        g_ckv[(((size_t)bh * 5 + p) * NCH + c) * DH + d] = kv[p];

    __shared__ float wred[5][2];
    const int lane = d & 31, w = d >> 5;
#pragma unroll
    for (int p = 0; p < 5; p++) {
        float v = rk[p];
#pragma unroll
        for (int o = 16; o > 0; o >>= 1) v += __shfl_down_sync(0xffffffffu, v, o);
        if (lane == 0) wred[p][w] = v;
    }
    __syncthreads();
    if (d == 0) {
#pragma unroll
        for (int p = 0; p < 5; p++)
            g_crk[((size_t)bh * 5 + p) * NCH + c] = wred[p][0] + wred[p][1];
    }
}

// ---------------------------------------------------------------------------
// Phase 2: block-parallel exclusive prefix over chunks.
// One block per bhp (=bh*5+p): 160 blocks x 1024 threads.
// ---------------------------------------------------------------------------
__global__ __launch_bounds__(1024) void prefix_kernel()
{
    const int bhp = blockIdx.x;          // 0..159
    const int tid = threadIdx.x;
    const int c  = tid >> 5;             // 0..31
    const int d0 = tid & 31;             // handles d0 and d0+32

    __shared__ float sm[2][NCH * DH];    // 2 x 8KB double buffer

    const size_t base = (size_t)bhp * NCH * DH;
    sm[0][c * DH + d0]      = g_ckv[base + c * DH + d0];
    sm[0][c * DH + d0 + 32] = g_ckv[base + c * DH + d0 + 32];
    __syncthreads();

    int src = 0;
#pragma unroll
    for (int st = 1; st < NCH; st <<= 1) {
        const int dst = src ^ 1;
        float v0 = sm[src][c * DH + d0];
        float v1 = sm[src][c * DH + d0 + 32];
        if (c >= st) {
            v0 += sm[src][(c - st) * DH + d0];
            v1 += sm[src][(c - st) * DH + d0 + 32];
        }
        sm[dst][c * DH + d0]      = v0;
        sm[dst][c * DH + d0 + 32] = v1;
        __syncthreads();
        src = dst;
    }

    float e0 = (c == 0) ? 0.0f : sm[src][(c - 1) * DH + d0];
    float e1 = (c == 0) ? 0.0f : sm[src][(c - 1) * DH + d0 + 32];
    g_ckv[base + c * DH + d0]      = e0;
    g_ckv[base + c * DH + d0 + 32] = e1;

    if (tid < 32) {
        const size_t rb = (size_t)bhp * NCH;
        float v = g_crk[rb + tid];
        float inc = v;
#pragma unroll
        for (int o = 1; o < 32; o <<= 1) {
            float t = __shfl_up_sync(0xffffffffu, inc, o);
            if (tid >= o) inc += t;
        }
        g_crk[rb + tid] = inc - v;
    }
}

// ---------------------------------------------------------------------------
// Phase 3 (fused den+final): one block per (b,h,chunk); 64 threads.
// q/k/v for the chunk staged once into smem (24KB); Phase A (den) and
// Phase B (rescan+output) both read smem.
// ---------------------------------------------------------------------------
__global__ __launch_bounds__(64) void den_final_kernel(Betas bt)
{
    const int blk = blockIdx.x;
    const int c = blk & 31, h = (blk >> 5) & 15, b = blk >> 9;
    const int bh = b * H_NUM + h;

    __shared__ float sq[CHS][DH];
    __shared__ float sk[CHS][DH];
    __shared__ float sv[CHS][DH];
    __shared__ float part[10][32];
    __shared__ float sden[CHS];

    // cooperative stage of the chunk's q/k/v
    {
        const int tid = threadIdx.x;
        const float* qb = g_qkv + ((size_t)(b * S_LEN + c * CHS)) * (3 * DMODEL) + h * DH;
        for (int i = tid; i < CHS * 16; i += 64) {
            int s = i >> 4, d4 = (i & 15) * 4;
            const float* row = qb + (size_t)s * (3 * DMODEL) + d4;
            *(float4*)&sq[s][d4] = *(const float4*)row;
            *(float4*)&sk[s][d4] = *(const float4*)(row + DMODEL);
            *(float4*)&sv[s][d4] = *(const float4*)(row + 2 * DMODEL);
        }
    }
    __syncthreads();

    // ---- Phase A: den for s = c*CHS + sl, sl = 0..31 ----
    {
        const int sl = threadIdx.x & 31;
        const int w  = threadIdx.x >> 5;
        const int db = w * 32;

        float Aq[5] = {0, 0, 0, 0, 0};
        float Rk[5] = {0, 0, 0, 0, 0};
#pragma unroll
        for (int j = 0; j < 32; j++) {
            float tq[5], tk[5];
            cheb5(clampx(sq[sl][db + j] * 0.125f), tq);
            cheb5(clampx(sk[sl][db + j] * 0.125f), tk);
#pragma unroll
            for (int p = 0; p < 5; p++) { Aq[p] += tq[p]; Rk[p] += tk[p]; }
        }

        if (w == 1) {
#pragma unroll
            for (int p = 0; p < 5; p++) { part[p][sl] = Aq[p]; part[5 + p][sl] = Rk[p]; }
        }
        __syncthreads();
        if (w == 0) {
#pragma unroll
            for (int p = 0; p < 5; p++) { Aq[p] += part[p][sl]; Rk[p] += part[5 + p][sl]; }

            float dsum = 0.0f;
#pragma unroll
            for (int p = 0; p < 5; p++) {
                float v = Rk[p];
#pragma unroll
                for (int o = 1; o < 32; o <<= 1) {
                    float t = __shfl_up_sync(0xffffffffu, v, o);
                    if (sl >= o) v += t;
                }
                float C = v + g_crk[((size_t)bh * 5 + p) * NCH + c];
                dsum += bt.b[p] * Aq[p] * C;
            }
            sden[sl] = dsum;
        }
        __syncthreads();
    }

    // ---- Phase B: rescan + output ----
    const int d = threadIdx.x;
    float kv[5];
#pragma unroll
    for (int p = 0; p < 5; p++)
        kv[p] = g_ckv[(((size_t)bh * 5 + p) * NCH + c) * DH + d];

    const size_t obase = ((size_t)(b * S_LEN + c * CHS)) * DMODEL + h * DH + d;

#pragma unroll 4
    for (int s = 0; s < CHS; s++) {
        float qv   = sq[s][d];
        float kval = sk[s][d];
        float vval = sv[s][d];

        float tk[5];
        cheb5(clampx(kval * 0.125f), tk);
#pragma unroll
        for (int p = 0; p < 5; p++) kv[p] += tk[p] * vval;

        float tq[5];
        cheb5(clampx(qv * 0.125f), tq);
        float num = 0.0f;
#pragma unroll
        for (int p = 0; p < 5; p++) num += bt.b[p] * tq[p] * kv[p];

        float res = num / (sden[s] + 1e-7f);
        __nv_bfloat16 hi = __float2bfloat16(res);
        size_t idx = obase + (size_t)s * DMODEL;
        g_ath[idx] = hi;
        g_atl[idx] = __float2bfloat16(res - __bfloat162float(hi));
    }
}

// ---------------------------------------------------------------------------
extern "C" void kernel_launch(void* const* d_in, const int* in_sizes, int n_in,
                              void* d_out, int out_size)
{
    const float* x     = (const float*)d_in[0];   // (2,1024,1024)
    const float* W_in  = (const float*)d_in[1];   // (3072,1024)
    const float* W_out = (const float*)d_in[2];   // (1024,1024)
    float* out = (float*)d_out;                   // (2,1024,1024)

    float* qkv;
    cudaGetSymbolAddress((void**)&qkv, g_qkv);
    __nv_bfloat16 *xh, *xl, *wih, *wil, *woh, *wol, *ath, *atl;
    cudaGetSymbolAddress((void**)&xh,  g_xh);
    cudaGetSymbolAddress((void**)&xl,  g_xl);
    cudaGetSymbolAddress((void**)&wih, g_wih);
    cudaGetSymbolAddress((void**)&wil, g_wil);
    cudaGetSymbolAddress((void**)&woh, g_woh);
    cudaGetSymbolAddress((void**)&wol, g_wol);
    cudaGetSymbolAddress((void**)&ath, g_ath);
    cudaGetSymbolAddress((void**)&atl, g_atl);

    // beta[p] = tail[p+1] / sum(tail[1..5])
    double alpha[6], tail[7];
    tail[6] = 0.0;
    for (int j = 5; j >= 0; j--) {
        alpha[j] = pow((double)(j + 1), -1.5);
        tail[j] = tail[j + 1] + alpha[j];
    }
    double bsum = tail[1] + tail[2] + tail[3] + tail[4] + tail[5];
    Betas bt;
    for (int p = 0; p < 5; p++) bt.b[p] = (float)(tail[p + 1] / bsum);

    const int M = BATCH * S_LEN;           // 2048
    const int nx = M * DMODEL;             // 2M
    const int nw1 = 3 * DMODEL * DMODEL;   // 3M
    const int nw2 = DMODEL * DMODEL;       // 1M

    cudaFuncSetAttribute(gemm_split, cudaFuncAttributeMaxDynamicSharedMemorySize, 98304);

    split3<<<(nx + nw1 + nw2) / 4 / 256, 256>>>(x, xh, xl, nx,
                                                W_in, wih, wil, nw1,
                                                W_out, woh, wol, nw2);
    gemm_split<<<dim3(3 * DMODEL / 128, M / 128), 256, 98304>>>(
        xh, xl, wih, wil, qkv, M, 3 * DMODEL, DMODEL);
    chunk_kernel<<<BATCH * H_NUM * NCH, 64>>>();
    prefix_kernel<<<BATCH * H_NUM * 5, 1024>>>();
    den_final_kernel<<<BATCH * H_NUM * NCH, 64>>>(bt);
    gemm_split<<<dim3(DMODEL / 128, M / 128), 256, 98304>>>(
        ath, atl, woh, wol, out, M, DMODEL, DMODEL);
}

// round 16
// speedup vs baseline: 1.1312x; 1.0133x over previous
#include <cuda_runtime.h>
#include <cuda_bf16.h>
#include <cstdint>
#include <cmath>

// Problem constants
#define S_LEN   1024
#define DMODEL  1024
#define H_NUM   16
#define DH      64
#define BATCH   2
#define NCH     32     // chunks along S
#define CHS     32     // chunk length (S_LEN / NCH)
#define NBLK    (BATCH * H_NUM * NCH)   // 1024 scan blocks
#define NBHP    (BATCH * H_NUM * 5)     // 160 prefix rows

// Scratch (static device globals; no allocation allowed)
__device__ float g_qkv[(size_t)BATCH * S_LEN * 3 * DMODEL];   // 25.2 MB
__device__ float g_ckv[NBHP * NCH * DH];                      // kv chunk sums -> exclusive prefix
__device__ float g_crk[NBHP * NCH];                           // rk chunk sums -> exclusive prefix
__device__ volatile unsigned g_bar1;
__device__ volatile unsigned g_bar2;

// bf16 hi/lo split operands
__device__ __nv_bfloat16 g_xh[(size_t)BATCH * S_LEN * DMODEL];
__device__ __nv_bfloat16 g_xl[(size_t)BATCH * S_LEN * DMODEL];
__device__ __nv_bfloat16 g_wih[(size_t)3 * DMODEL * DMODEL];
__device__ __nv_bfloat16 g_wil[(size_t)3 * DMODEL * DMODEL];
__device__ __nv_bfloat16 g_woh[(size_t)DMODEL * DMODEL];
__device__ __nv_bfloat16 g_wol[(size_t)DMODEL * DMODEL];
__device__ __nv_bfloat16 g_ath[(size_t)BATCH * S_LEN * DMODEL];
__device__ __nv_bfloat16 g_atl[(size_t)BATCH * S_LEN * DMODEL];

struct Betas { float b[5]; };

__device__ __forceinline__ float clampx(float x) {
    return fminf(fmaxf(x, -1.0f + 1e-6f), 1.0f - 1e-6f);
}

__device__ __forceinline__ void cheb5(float x, float t[5]) {
    float x2 = x + x;
    float t1 = x;
    float t2 = x2 * t1 - 1.0f;
    float t3 = x2 * t2 - t1;
    float t4 = x2 * t3 - t2;
    float t5 = x2 * t4 - t3;
    t[0] = t1; t[1] = t2; t[2] = t3; t[3] = t4; t[4] = t5;
}

__device__ __forceinline__ unsigned pack2(__nv_bfloat16 a, __nv_bfloat16 b) {
    __nv_bfloat162 t(a, b);
    return *reinterpret_cast<unsigned*>(&t);
}

__device__ __forceinline__ void ldsm4(unsigned& r0, unsigned& r1, unsigned& r2, unsigned& r3,
                                      unsigned addr) {
    asm volatile("ldmatrix.sync.aligned.m8n8.x4.shared.b16 {%0,%1,%2,%3}, [%4];"
                 : "=r"(r0), "=r"(r1), "=r"(r2), "=r"(r3) : "r"(addr));
}

__device__ __forceinline__ void mma_bf16(float c[4],
                                         unsigned a0, unsigned a1, unsigned a2, unsigned a3,
                                         unsigned b0, unsigned b1) {
    asm volatile(
        "mma.sync.aligned.m16n8k16.row.col.f32.bf16.bf16.f32 "
        "{%0,%1,%2,%3}, {%4,%5,%6,%7}, {%8,%9}, {%0,%1,%2,%3};"
        : "+f"(c[0]), "+f"(c[1]), "+f"(c[2]), "+f"(c[3])
        : "r"(a0), "r"(a1), "r"(a2), "r"(a3), "r"(b0), "r"(b1));
}

#define CP16(dst, src) \
    asm volatile("cp.async.cg.shared.global [%0], [%1], 16;" :: "r"(dst), "l"(src))
#define CP_COMMIT() asm volatile("cp.async.commit_group;")
#define CP_WAIT1()  asm volatile("cp.async.wait_group 1;")
#define CP_WAIT0()  asm volatile("cp.async.wait_group 0;")

// swizzled byte offset inside a 128x32 bf16 tile (64B rows).
__device__ __forceinline__ unsigned swz(int m, int cbyte) {
    return (unsigned)((m << 6) + (cbyte ^ (((m >> 1) & 3) << 4)));
}

// ---------------------------------------------------------------------------
// split3: f32 -> bf16 hi + bf16 lo residual; also resets the scan barriers
// (stream-ordered: completes before scan_fused launches).
// ---------------------------------------------------------------------------
__global__ __launch_bounds__(256) void split3(
    const float* __restrict__ a, __nv_bfloat16* __restrict__ ah, __nv_bfloat16* __restrict__ al, int na,
    const float* __restrict__ b, __nv_bfloat16* __restrict__ bh, __nv_bfloat16* __restrict__ bl, int nb,
    const float* __restrict__ c, __nv_bfloat16* __restrict__ ch, __nv_bfloat16* __restrict__ cl, int nc)
{
    if (blockIdx.x == 0 && threadIdx.x == 0) { g_bar1 = 0u; g_bar2 = 0u; }

    int i = (blockIdx.x * blockDim.x + threadIdx.x) * 4;
    const float* src; __nv_bfloat16 *hi, *lo; int off;
    if (i < na)           { src = a; hi = ah; lo = al; off = i; }
    else if (i < na + nb) { src = b; hi = bh; lo = bl; off = i - na; }
    else if (i < na + nb + nc) { src = c; hi = ch; lo = cl; off = i - na - nb; }
    else return;

    float4 v = *(const float4*)(src + off);
    __nv_bfloat16 h0 = __float2bfloat16(v.x), h1 = __float2bfloat16(v.y);
    __nv_bfloat16 h2 = __float2bfloat16(v.z), h3 = __float2bfloat16(v.w);
    __nv_bfloat16 l0 = __float2bfloat16(v.x - __bfloat162float(h0));
    __nv_bfloat16 l1 = __float2bfloat16(v.y - __bfloat162float(h1));
    __nv_bfloat16 l2 = __float2bfloat16(v.z - __bfloat162float(h2));
    __nv_bfloat16 l3 = __float2bfloat16(v.w - __bfloat162float(h3));
    *(uint2*)(hi + off) = make_uint2(pack2(h0, h1), pack2(h2, h3));
    *(uint2*)(lo + off) = make_uint2(pack2(l0, l1), pack2(l2, l3));
}

// ---------------------------------------------------------------------------
// bf16x3 GEMM, pre-split operands, 3-stage cp.async pipeline (1 sync/tile):
//   C[M,N] = (Ah+Al)[M,K] @ (Bh+Bl)[N,K]^T  (drop Al*Bl)
// BM=BN=128, BK=32, 256 threads (8 warps 2x4), warp tile 64x32.
// Dynamic smem: 3 stages x 32KB -> 96KB; 2 CTAs/SM resident.
// ---------------------------------------------------------------------------
__global__ __launch_bounds__(256) void gemm_split(
    const __nv_bfloat16* __restrict__ Ahg, const __nv_bfloat16* __restrict__ Alg,
    const __nv_bfloat16* __restrict__ Bhg, const __nv_bfloat16* __restrict__ Blg,
    float* __restrict__ C, int M, int N, int K)
{
    extern __shared__ char dsmem[];
    const unsigned smem_u32 = (unsigned)__cvta_generic_to_shared(dsmem);

    const int tid  = threadIdx.x;
    const int wid  = tid >> 5;
    const int lane = tid & 31;
    const int wm = (wid >> 2) * 64;
    const int wn = (wid & 3) * 32;

    const int bm = blockIdx.y * 128;
    const int bn = blockIdx.x * 128;

    int crow[2], ccb[2];
    size_t aoff[2], boff[2];
    unsigned dsw[2];
#pragma unroll
    for (int i = 0; i < 2; i++) {
        int c = tid + i * 256;
        crow[i] = c >> 2;
        ccb[i]  = (c & 3) * 16;
        aoff[i] = (size_t)(bm + crow[i]) * K * 2 + ccb[i];
        boff[i] = (size_t)(bn + crow[i]) * K * 2 + ccb[i];
        dsw[i]  = swz(crow[i], ccb[i]);
    }
    const char* Ahc = (const char*)Ahg;
    const char* Alc = (const char*)Alg;
    const char* Bhc = (const char*)Bhg;
    const char* Blc = (const char*)Blg;

    auto issue_stage = [&](int stg, int k0) {
        unsigned sb = smem_u32 + (unsigned)stg * 32768u;
        size_t kb = (size_t)k0 * 2;
#pragma unroll
        for (int i = 0; i < 2; i++) {
            unsigned d = sb + dsw[i];
            CP16(d,          Ahc + aoff[i] + kb);
            CP16(d + 8192u,  Alc + aoff[i] + kb);
            CP16(d + 16384u, Bhc + boff[i] + kb);
            CP16(d + 24576u, Blc + boff[i] + kb);
        }
        CP_COMMIT();
    };

    float acc[4][4][4];
#pragma unroll
    for (int i = 0; i < 4; i++)
#pragma unroll
        for (int j = 0; j < 4; j++)
#pragma unroll
            for (int r = 0; r < 4; r++) acc[i][j][r] = 0.0f;

    const int lt = lane >> 3, lr = lane & 7;
    unsigned a_base[4], b_base[2];
#pragma unroll
    for (int mf = 0; mf < 4; mf++) {
        int m = wm + mf * 16 + (lt & 1) * 8 + lr;
        a_base[mf] = swz(m, (lt >> 1) * 16);
    }
#pragma unroll
    for (int np = 0; np < 2; np++) {
        int n = wn + np * 16 + (lt >> 1) * 8 + lr;
        b_base[np] = swz(n, (lt & 1) * 16);
    }

    const int nk = K / 32;
    issue_stage(0, 0);
    issue_stage(1, 32);

    int cur = 0, nxt = 2;
    for (int kt = 0; kt < nk; kt++) {
        if (kt + 2 < nk) { CP_WAIT1(); } else { CP_WAIT0(); }
        __syncthreads();
        if (kt + 2 < nk) issue_stage(nxt, (kt + 2) * 32);

        const unsigned st = smem_u32 + (unsigned)cur * 32768u;
        const unsigned sAh = st, sAl = st + 8192u, sBh = st + 16384u, sBl = st + 24576u;

#pragma unroll
        for (int kk = 0; kk < 2; kk++) {
            const unsigned kb = kk * 32;   // XOR advance (bit 5 within swizzle field)
            unsigned ah[4][4], al[4][4];
#pragma unroll
            for (int mf = 0; mf < 4; mf++) {
                ldsm4(ah[mf][0], ah[mf][1], ah[mf][2], ah[mf][3], sAh + (a_base[mf] ^ kb));
                ldsm4(al[mf][0], al[mf][1], al[mf][2], al[mf][3], sAl + (a_base[mf] ^ kb));
            }
            unsigned bhf[4][2], blf[4][2];
#pragma unroll
            for (int np = 0; np < 2; np++) {
                ldsm4(bhf[2 * np][0], bhf[2 * np][1], bhf[2 * np + 1][0], bhf[2 * np + 1][1],
                      sBh + (b_base[np] ^ kb));
                ldsm4(blf[2 * np][0], blf[2 * np][1], blf[2 * np + 1][0], blf[2 * np + 1][1],
                      sBl + (b_base[np] ^ kb));
            }
            // Pass 1: hh
#pragma unroll
            for (int mf = 0; mf < 4; mf++)
#pragma unroll
                for (int nf = 0; nf < 4; nf++)
                    mma_bf16(acc[mf][nf], ah[mf][0], ah[mf][1], ah[mf][2], ah[mf][3],
                             bhf[nf][0], bhf[nf][1]);
            // Pass 2: hl
#pragma unroll
            for (int mf = 0; mf < 4; mf++)
#pragma unroll
                for (int nf = 0; nf < 4; nf++)
                    mma_bf16(acc[mf][nf], ah[mf][0], ah[mf][1], ah[mf][2], ah[mf][3],
                             blf[nf][0], blf[nf][1]);
            // Pass 3: lh
#pragma unroll
            for (int mf = 0; mf < 4; mf++)
#pragma unroll
                for (int nf = 0; nf < 4; nf++)
                    mma_bf16(acc[mf][nf], al[mf][0], al[mf][1], al[mf][2], al[mf][3],
                             bhf[nf][0], bhf[nf][1]);
        }
        cur = (cur + 1 == 3) ? 0 : cur + 1;
        nxt = (nxt + 1 == 3) ? 0 : nxt + 1;
    }

    const int g = lane >> 2, th = lane & 3;
#pragma unroll
    for (int mf = 0; mf < 4; mf++) {
#pragma unroll
        for (int nf = 0; nf < 4; nf++) {
            int row = bm + wm + mf * 16 + g;
            int col = bn + wn + nf * 8 + 2 * th;
            *(float2*)(C + (size_t)row * N + col) =
                make_float2(acc[mf][nf][0], acc[mf][nf][1]);
            *(float2*)(C + (size_t)(row + 8) * N + col) =
                make_float2(acc[mf][nf][2], acc[mf][nf][3]);
        }
    }
}

// ---------------------------------------------------------------------------
// scan_fused: chunk sums + cross-chunk prefix + den + final in ONE persistent
// kernel. 1024 blocks x 64 threads, all co-resident (26KB smem -> 8/SM = 1184).
// Global software barriers via atomic counters (reset by split3).
// ---------------------------------------------------------------------------
__global__ __launch_bounds__(64) void scan_fused(Betas bt)
{
    const int blk = blockIdx.x;                 // b*512 + h*32 + c
    const int c = blk & 31, h = (blk >> 5) & 15, b = blk >> 9;
    const int bh = b * H_NUM + h;
    const int tid = threadIdx.x;
    const int d = tid;

    __shared__ float sq[CHS][DH];
    __shared__ float sk[CHS][DH];
    __shared__ float sv[CHS][DH];
    __shared__ float part[10][32];
    __shared__ float sden[CHS];

    // ---- stage q/k/v for this chunk (once; reused by all phases) ----
    {
        const float* qb = g_qkv + ((size_t)(b * S_LEN + c * CHS)) * (3 * DMODEL) + h * DH;
        for (int i = tid; i < CHS * 16; i += 64) {
            int s = i >> 4, d4 = (i & 15) * 4;
            const float* row = qb + (size_t)s * (3 * DMODEL) + d4;
            *(float4*)&sq[s][d4] = *(const float4*)row;
            *(float4*)&sk[s][d4] = *(const float4*)(row + DMODEL);
            *(float4*)&sv[s][d4] = *(const float4*)(row + 2 * DMODEL);
        }
    }
    __syncthreads();

    // ---- Phase 1: chunk sums ----
    {
        float kv[5] = {0, 0, 0, 0, 0};
        float rk[5] = {0, 0, 0, 0, 0};
#pragma unroll 4
        for (int s = 0; s < CHS; s++) {
            float t[5];
            cheb5(clampx(sk[s][d] * 0.125f), t);
            float vval = sv[s][d];
#pragma unroll
            for (int p = 0; p < 5; p++) { kv[p] += t[p] * vval; rk[p] += t[p]; }
        }
#pragma unroll
        for (int p = 0; p < 5; p++)
            g_ckv[(((size_t)bh * 5 + p) * NCH + c) * DH + d] = kv[p];

        const int lane = d & 31, w = d >> 5;
#pragma unroll
        for (int p = 0; p < 5; p++) {
            float v = rk[p];
#pragma unroll
            for (int o = 16; o > 0; o >>= 1) v += __shfl_down_sync(0xffffffffu, v, o);
            if (lane == 0) part[p][w] = v;   // reuse part[] as scratch
        }
        __syncthreads();
        if (d == 0) {
#pragma unroll
            for (int p = 0; p < 5; p++)
                g_crk[((size_t)bh * 5 + p) * NCH + c] = part[p][0] + part[p][1];
        }
    }
    __threadfence();
    __syncthreads();
    if (tid == 0) atomicAdd((unsigned*)&g_bar1, 1u);

    // ---- Phase 2: prefix (blocks 0..159, bhp = blk) ----
    if (blk < NBHP) {
        if (tid == 0) { while (g_bar1 < (unsigned)NBLK) __nanosleep(128); }
        __syncthreads();
        __threadfence();

        const size_t base = (size_t)blk * NCH * DH + d;
        float vals[NCH];
#pragma unroll
        for (int i = 0; i < NCH; i++) vals[i] = g_ckv[base + (size_t)i * DH];
        float run = 0.0f;
#pragma unroll
        for (int i = 0; i < NCH; i++) {
            g_ckv[base + (size_t)i * DH] = run;
            run += vals[i];
        }
        if (tid < 32) {
            const size_t rb = (size_t)blk * NCH;
            float v = g_crk[rb + tid];
            float inc = v;
#pragma unroll
            for (int o = 1; o < 32; o <<= 1) {
                float t = __shfl_up_sync(0xffffffffu, inc, o);
                if (tid >= o) inc += t;
            }
            g_crk[rb + tid] = inc - v;
        }
        __threadfence();
        __syncthreads();
        if (tid == 0) atomicAdd((unsigned*)&g_bar2, 1u);
    }

    // ---- wait for all prefixes ----
    if (tid == 0) { while (g_bar2 < (unsigned)NBHP) __nanosleep(128); }
    __syncthreads();
    __threadfence();

    // ---- Phase 3a: den (from staged smem) ----
    {
        const int sl = tid & 31;
        const int w  = tid >> 5;
        const int db = w * 32;

        float Aq[5] = {0, 0, 0, 0, 0};
        float Rk[5] = {0, 0, 0, 0, 0};
#pragma unroll
        for (int j = 0; j < 32; j++) {
            float tq[5], tk[5];
            cheb5(clampx(sq[sl][db + j] * 0.125f), tq);
            cheb5(clampx(sk[sl][db + j] * 0.125f), tk);
#pragma unroll
            for (int p = 0; p < 5; p++) { Aq[p] += tq[p]; Rk[p] += tk[p]; }
        }

        __syncthreads();   // part[] scratch reuse safety
        if (w == 1) {
#pragma unroll
            for (int p = 0; p < 5; p++) { part[p][sl] = Aq[p]; part[5 + p][sl] = Rk[p]; }
        }
        __syncthreads();
        if (w == 0) {
#pragma unroll
            for (int p = 0; p < 5; p++) { Aq[p] += part[p][sl]; Rk[p] += part[5 + p][sl]; }

            float dsum = 0.0f;
#pragma unroll
            for (int p = 0; p < 5; p++) {
                float v = Rk[p];
#pragma unroll
                for (int o = 1; o < 32; o <<= 1) {
                    float t = __shfl_up_sync(0xffffffffu, v, o);
                    if (sl >= o) v += t;
                }
                float C = v + g_crk[((size_t)bh * 5 + p) * NCH + c];
                dsum += bt.b[p] * Aq[p] * C;
            }
            sden[sl] = dsum;
        }
        __syncthreads();
    }

    // ---- Phase 3b: rescan + output ----
    float kv[5];
#pragma unroll
    for (int p = 0; p < 5; p++)
        kv[p] = g_ckv[(((size_t)bh * 5 + p) * NCH + c) * DH + d];

    const size_t obase = ((size_t)(b * S_LEN + c * CHS)) * DMODEL + h * DH + d;

#pragma unroll 4
    for (int s = 0; s < CHS; s++) {
        float qv   = sq[s][d];
        float kval = sk[s][d];
        float vval = sv[s][d];

        float tk[5];
        cheb5(clampx(kval * 0.125f), tk);
#pragma unroll
        for (int p = 0; p < 5; p++) kv[p] += tk[p] * vval;

        float tq[5];
        cheb5(clampx(qv * 0.125f), tq);
        float num = 0.0f;
#pragma unroll
        for (int p = 0; p < 5; p++) num += bt.b[p] * tq[p] * kv[p];

        float res = num / (sden[s] + 1e-7f);
        __nv_bfloat16 hi = __float2bfloat16(res);
        size_t idx = obase + (size_t)s * DMODEL;
        g_ath[idx] = hi;
        g_atl[idx] = __float2bfloat16(res - __bfloat162float(hi));
    }
}

// ---------------------------------------------------------------------------
extern "C" void kernel_launch(void* const* d_in, const int* in_sizes, int n_in,
                              void* d_out, int out_size)
{
    const float* x     = (const float*)d_in[0];   // (2,1024,1024)
    const float* W_in  = (const float*)d_in[1];   // (3072,1024)
    const float* W_out = (const float*)d_in[2];   // (1024,1024)
    float* out = (float*)d_out;                   // (2,1024,1024)

    float* qkv;
    cudaGetSymbolAddress((void**)&qkv, g_qkv);
    __nv_bfloat16 *xh, *xl, *wih, *wil, *woh, *wol, *ath, *atl;
    cudaGetSymbolAddress((void**)&xh,  g_xh);
    cudaGetSymbolAddress((void**)&xl,  g_xl);
    cudaGetSymbolAddress((void**)&wih, g_wih);
    cudaGetSymbolAddress((void**)&wil, g_wil);
    cudaGetSymbolAddress((void**)&woh, g_woh);
    cudaGetSymbolAddress((void**)&wol, g_wol);
    cudaGetSymbolAddress((void**)&ath, g_ath);
    cudaGetSymbolAddress((void**)&atl, g_atl);

    // beta[p] = tail[p+1] / sum(tail[1..5])
    double alpha[6], tail[7];
    tail[6] = 0.0;
    for (int j = 5; j >= 0; j--) {
        alpha[j] = pow((double)(j + 1), -1.5);
        tail[j] = tail[j + 1] + alpha[j];
    }
    double bsum = tail[1] + tail[2] + tail[3] + tail[4] + tail[5];
    Betas bt;
    for (int p = 0; p < 5; p++) bt.b[p] = (float)(tail[p + 1] / bsum);

    const int M = BATCH * S_LEN;           // 2048
    const int nx = M * DMODEL;             // 2M
    const int nw1 = 3 * DMODEL * DMODEL;   // 3M
    const int nw2 = DMODEL * DMODEL;       // 1M

    cudaFuncSetAttribute(gemm_split, cudaFuncAttributeMaxDynamicSharedMemorySize, 98304);

    split3<<<(nx + nw1 + nw2) / 4 / 256, 256>>>(x, xh, xl, nx,
                                                W_in, wih, wil, nw1,
                                                W_out, woh, wol, nw2);
    gemm_split<<<dim3(3 * DMODEL / 128, M / 128), 256, 98304>>>(
        xh, xl, wih, wil, qkv, M, 3 * DMODEL, DMODEL);
    scan_fused<<<NBLK, 64>>>(bt);
    gemm_split<<<dim3(DMODEL / 128, M / 128), 256, 98304>>>(
        ath, atl, woh, wol, out, M, DMODEL, DMODEL);
}